// round 1
// baseline (speedup 1.0000x reference)
#include <cuda_runtime.h>
#include <math.h>

// CNO_LReLu: antialiased bicubic upsample x2 (2048->4096), LeakyReLU(0.01),
// antialiased bicubic downsample x2 (4096->2048), per (b,c) row. B*C = 8192 rows.
//
// Fully fused: one block per row; input row staged in smem; stage-1 values held
// in registers per thread (sliding window); interior weights are exact fp32
// immediate constants (FFMA-imm form); row-edge outputs use a generic
// renormalized path matching the reference exactly.

#define IN_SIZE  2048
#define MID_SIZE 4096
#define OUT_SIZE 2048
#define NROWS    8192
#define TPB      512        // 4 outputs per thread

__device__ __forceinline__ float keys_cubic(float x) {
    // Keys cubic, a = -0.5 (exact fp32 for the dyadic abscissae that occur here)
    float ax = fabsf(x);
    if (ax <= 1.0f) return (1.5f * ax - 2.5f) * ax * ax + 1.0f;
    if (ax <  2.0f) return -0.5f * ((((ax - 5.0f) * ax + 8.0f) * ax) - 4.0f);
    return 0.0f;
}

__device__ __forceinline__ float lrelu(float v) {
    // max(v, 0.01*v) == LeakyReLU(0.01) for all v
    return fmaxf(v, 0.01f * v);
}

// Generic stage-1 value (handles OOB-tap drop + renormalization at row edges).
__device__ float y1_generic(const float* __restrict__ xs, int o) {
    float center = ((float)o + 0.5f) * 0.5f;
    int xmin = (int)floorf(center - 1.5f);   // center - support + 0.5, support = 2
    float acc = 0.0f, ws = 0.0f;
    #pragma unroll
    for (int t = 0; t < 5; ++t) {
        int idx = xmin + t;
        float w = keys_cubic(((float)idx + 0.5f) - center);
        if (idx >= 0 && idx < IN_SIZE) { ws += w; acc += w * xs[idx]; }
    }
    return acc / ws;
}

// Generic final output (stage-2 with renorm; stage-1 taps via y1_generic).
__device__ float out_generic(const float* __restrict__ xs, int o2) {
    float center = ((float)o2 + 0.5f) * 2.0f;
    int xmin = (int)floorf(center - 3.5f);   // center - support + 0.5, support = 4
    float acc = 0.0f, ws = 0.0f;
    #pragma unroll
    for (int t = 0; t < 9; ++t) {
        int idx = xmin + t;
        float w = keys_cubic((((float)idx + 0.5f) - center) * 0.5f);
        if (idx >= 0 && idx < MID_SIZE) { ws += w; acc += w * lrelu(y1_generic(xs, idx)); }
    }
    return acc / ws;
}

__global__ void __launch_bounds__(TPB, 2)
cno_lrelu_kernel(const float* __restrict__ x, float* __restrict__ out) {
    __shared__ float xs[IN_SIZE];

    const int row = blockIdx.x;
    const float* __restrict__ xr = x + (size_t)row * IN_SIZE;
    float* __restrict__ orow = out + (size_t)row * OUT_SIZE;

    // Stage row into smem: 512 threads x one float4 = 2048 floats, coalesced.
    reinterpret_cast<float4*>(xs)[threadIdx.x] =
        reinterpret_cast<const float4*>(xr)[threadIdx.x];
    __syncthreads();

    const int t = threadIdx.x;

    if (t == 0 || t == TPB - 1) {
        // Row-edge chunk: generic renormalized path (matches reference's
        // drop-OOB-taps + renormalize semantics exactly).
        float4 o4;
        o4.x = out_generic(xs, 4 * t + 0);
        o4.y = out_generic(xs, 4 * t + 1);
        o4.z = out_generic(xs, 4 * t + 2);
        o4.w = out_generic(xs, 4 * t + 3);
        reinterpret_cast<float4*>(orow)[t] = o4;
        return;
    }

    // ---- Fast interior path: thread owns outputs o2 = 4t .. 4t+3 ----
    // Needs stage-1 values y[j] for mid-index o = 8t-3 .. 8t+10  (14 values),
    // which need input x[4t-3 .. 4t+6]. Load x[4(t-1) .. 4(t-1)+11] as 3
    // conflict-free LDS.128 (t >= 1 guarantees in-bounds; max 4t+7 <= 2047).
    float xv[12];
    #pragma unroll
    for (int q = 0; q < 3; ++q)
        *reinterpret_cast<float4*>(&xv[4 * q]) =
            *reinterpret_cast<const float4*>(&xs[4 * (t - 1) + 4 * q]);

    // Stage 1 + LeakyReLU. y[j] corresponds to mid index o = 8t-3+j.
    // j even -> o odd  -> taps x[k-1..k+2], weights W_O
    // j odd  -> o even -> taps x[k-2..k+1], weights W_E
    // Both cases start at local xv index (j>>1)+1 (base offset 4t-4).
    float yv[14];
    #pragma unroll
    for (int j = 0; j < 14; ++j) {
        const int s = (j >> 1) + 1;
        float v;
        if ((j & 1) == 0) {
            v = fmaf(-0.0703125f, xv[s],
                fmaf( 0.8671875f, xv[s + 1],
                fmaf( 0.2265625f, xv[s + 2], -0.0234375f * xv[s + 3])));
        } else {
            v = fmaf(-0.0234375f, xv[s],
                fmaf( 0.2265625f, xv[s + 1],
                fmaf( 0.8671875f, xv[s + 2], -0.0703125f * xv[s + 3])));
        }
        yv[j] = fmaxf(v, 0.01f * v);
    }

    // Stage 2: out(o2 = 4t+i) = sum_{u=0..7} W2[u] * y[2i+u]  (tap 8 is 0).
    float4 o4;
    float* op = &o4.x;
    #pragma unroll
    for (int i = 0; i < 4; ++i) {
        const int s = 2 * i;
        float a =  fmaf(-0.01171875f, yv[s],     -0.03515625f * yv[s + 1]);
        a = fmaf( 0.11328125f, yv[s + 2], a);
        a = fmaf( 0.43359375f, yv[s + 3], a);
        a = fmaf( 0.43359375f, yv[s + 4], a);
        a = fmaf( 0.11328125f, yv[s + 5], a);
        a = fmaf(-0.03515625f, yv[s + 6], a);
        a = fmaf(-0.01171875f, yv[s + 7], a);
        op[i] = a;
    }
    reinterpret_cast<float4*>(orow)[t] = o4;   // coalesced STG.128
}

extern "C" void kernel_launch(void* const* d_in, const int* in_sizes, int n_in,
                              void* d_out, int out_size) {
    const float* x = (const float*)d_in[0];
    float* out = (float*)d_out;
    cno_lrelu_kernel<<<NROWS, TPB>>>(x, out);
}

// round 9
// speedup vs baseline: 5.5030x; 5.5030x over previous
#include <cuda_runtime.h>
#include <math.h>

// CNO_LReLu: antialiased bicubic upsample x2 (2048->4096), LeakyReLU(0.01),
// antialiased bicubic downsample x2 (4096->2048), per (b,c) row. B*C = 8192 rows.
//
// R2 kernel, eighth submission (seven GPU-broker timeouts; never yet benched).
// All edge weights analytically verified against the reference resize plan
// (drop-OOB-taps + renormalize). Every thread is a short straight-line
// FFMA-imm sequence; no generic cubic path remains.

#define IN_SIZE  2048
#define OUT_SIZE 2048
#define NROWS    8192
#define TPB      512        // 4 outputs per thread

// Interior upsample weight vectors (exact Keys-cubic values, sum = 1):
//   odd  mid-index o: taps x[(o-1)/2-1 .. +2],  W_O
//   even mid-index o: taps x[o/2-2    .. +1],  W_E
#define WO4(a,b,c,d) fmaf(-0.0703125f,(a), fmaf(0.8671875f,(b), fmaf(0.2265625f,(c), -0.0234375f*(d))))
#define WE4(a,b,c,d) fmaf(-0.0234375f,(a), fmaf(0.2265625f,(b), fmaf(0.8671875f,(c), -0.0703125f*(d))))

__device__ __forceinline__ float lrelu(float v) {
    return fmaxf(v, 0.01f * v);   // == LeakyReLU(0.01)
}

// Interior stage-2: out = W2 . z[0..7]  (9th tap weight is exactly 0)
__device__ __forceinline__ float stage2(const float* __restrict__ z) {
    float a =  fmaf(-0.01171875f, z[0], -0.03515625f * z[1]);
    a = fmaf( 0.11328125f, z[2], a);
    a = fmaf( 0.43359375f, z[3], a);
    a = fmaf( 0.43359375f, z[4], a);
    a = fmaf( 0.11328125f, z[5], a);
    a = fmaf(-0.03515625f, z[6], a);
    a = fmaf(-0.01171875f, z[7], a);
    return a;
}

__global__ void __launch_bounds__(TPB, 3)
cno_lrelu_kernel(const float* __restrict__ x, float* __restrict__ out) {
    __shared__ float xs[IN_SIZE];

    const int row = blockIdx.x;
    const float* __restrict__ xr = x + (size_t)row * IN_SIZE;
    float* __restrict__ orow = out + (size_t)row * OUT_SIZE;

    // Stage row into smem: 512 threads x one float4, coalesced.
    reinterpret_cast<float4*>(xs)[threadIdx.x] =
        reinterpret_cast<const float4*>(xr)[threadIdx.x];
    __syncthreads();

    const int t = threadIdx.x;

    // 12-float window; for interior threads base = 4t-4 so that the window
    // covers x[4t-3 .. 4t+6] needed by outputs 4t..4t+3.
    const int base = (t == 0) ? 0 : ((t == TPB - 1) ? (IN_SIZE - 12) : 4 * (t - 1));

    float xv[12];
    #pragma unroll
    for (int q = 0; q < 3; ++q)
        *reinterpret_cast<float4*>(&xv[4 * q]) =
            *reinterpret_cast<const float4*>(&xs[base + 4 * q]);

    float4 o4;

    if (t == 0) {
        // ---- Left edge: outputs 0..3 need mid y[0..10]; y[0..2] are special ----
        float z[11];
        z[0] = fmaf(0.8671875f, xv[0], -0.0703125f * xv[1]) * (1.0f / 0.796875f);
        z[1] = fmaf(0.8671875f, xv[0], fmaf(0.2265625f, xv[1], -0.0234375f * xv[2])) * (1.0f / 1.0703125f);
        z[2] = fmaf(0.2265625f, xv[0], fmaf(0.8671875f, xv[1], -0.0703125f * xv[2])) * (1.0f / 1.0234375f);
        #pragma unroll
        for (int m = 3; m <= 10; ++m) {
            const int s = (m - 3) >> 1;
            z[m] = (m & 1) ? WO4(xv[s], xv[s+1], xv[s+2], xv[s+3])
                           : WE4(xv[s], xv[s+1], xv[s+2], xv[s+3]);
        }
        #pragma unroll
        for (int m = 0; m <= 10; ++m) z[m] = lrelu(z[m]);

        o4.x = fmaf(0.8671875f, z[0] + z[1],
               fmaf(0.2265625f, z[2],
               fmaf(-0.0703125f, z[3], -0.0234375f * z[4]))) * (1.0f / 1.8671875f);
        o4.y = (fmaf(-0.0703125f, z[0],
                fmaf( 0.2265625f, z[1],
                fmaf( 0.8671875f, z[2] + z[3],
                fmaf( 0.2265625f, z[4],
                fmaf(-0.0703125f, z[5], -0.0234375f * z[6])))))) * (1.0f / 2.0234375f);
        o4.z = stage2(z + 1);
        o4.w = stage2(z + 3);
    } else if (t == TPB - 1) {
        // ---- Right edge: outputs 2044..2047 need mid y[4085..4095] ----
        // base = 2036: xv[i] = x[2036+i]. z[j] = y[4085+j].
        float z[11];
        #pragma unroll
        for (int j = 0; j <= 7; ++j) {
            const int s = (j >> 1) + 5;   // j=0 -> y[4085] (odd) taps x[2041..2044] = xv[5..8]
            z[j] = (j & 1) ? WE4(xv[s], xv[s+1], xv[s+2], xv[s+3])
                           : WO4(xv[s], xv[s+1], xv[s+2], xv[s+3]);
        }
        z[8]  = fmaf(-0.0703125f, xv[9], fmaf(0.8671875f, xv[10], 0.2265625f * xv[11])) * (1.0f / 1.0234375f);
        z[9]  = fmaf(-0.0234375f, xv[9], fmaf(0.2265625f, xv[10], 0.8671875f * xv[11])) * (1.0f / 1.0703125f);
        z[10] = fmaf(-0.0703125f, xv[10], 0.8671875f * xv[11]) * (1.0f / 0.796875f);
        #pragma unroll
        for (int m = 0; m <= 10; ++m) z[m] = lrelu(z[m]);

        o4.x = stage2(z + 0);   // out 2044
        o4.y = stage2(z + 2);   // out 2045
        o4.z = (fmaf(-0.0703125f, z[10],
                fmaf( 0.2265625f, z[9],
                fmaf( 0.8671875f, z[8] + z[7],
                fmaf( 0.2265625f, z[6],
                fmaf(-0.0703125f, z[5], -0.0234375f * z[4])))))) * (1.0f / 2.0234375f);
        o4.w = fmaf(0.8671875f, z[10] + z[9],
               fmaf(0.2265625f, z[8],
               fmaf(-0.0703125f, z[7], -0.0234375f * z[6]))) * (1.0f / 1.8671875f);
    } else {
        // ---- Interior: outputs 4t..4t+3, mid y[8t-3 .. 8t+10] ----
        float yv[14];
        #pragma unroll
        for (int j = 0; j < 14; ++j) {
            const int s = (j >> 1) + 1;
            float v = ((j & 1) == 0)
                ? WO4(xv[s], xv[s+1], xv[s+2], xv[s+3])
                : WE4(xv[s], xv[s+1], xv[s+2], xv[s+3]);
            yv[j] = fmaxf(v, 0.01f * v);
        }
        o4.x = stage2(yv + 0);
        o4.y = stage2(yv + 2);
        o4.z = stage2(yv + 4);
        o4.w = stage2(yv + 6);
    }

    reinterpret_cast<float4*>(orow)[t] = o4;   // coalesced STG.128
}

extern "C" void kernel_launch(void* const* d_in, const int* in_sizes, int n_in,
                              void* d_out, int out_size) {
    const float* x = (const float*)d_in[0];
    float* out = (float*)d_out;
    cno_lrelu_kernel<<<NROWS, TPB>>>(x, out);
}

// round 10
// speedup vs baseline: 5.6080x; 1.0191x over previous
#include <cuda_runtime.h>
#include <math.h>

// CNO_LReLu: antialiased bicubic upsample x2 (2048->4096), LeakyReLU(0.01),
// antialiased bicubic downsample x2 (4096->2048), per (b,c) row. B*C = 8192 rows.
//
// R10: interior path packed with f32x2 (FFMA2). Stage-1 pairs y[2k],y[2k+1]
// share the same 4 taps with different weights -> one fma.rn.f32x2 per tap.
// Stage-2 uses packed weight pairs + one horizontal add per output.
// Interior fma-pipe ops: 116 -> ~76. Edge threads keep the verified scalar path.

#define IN_SIZE  2048
#define OUT_SIZE 2048
#define NROWS    8192
#define TPB      512        // 4 outputs per thread

typedef unsigned long long u64;

__device__ __forceinline__ u64 pack2(float a, float b) {
    u64 r;
    asm("mov.b64 %0, {%1, %2};" : "=l"(r)
        : "r"(__float_as_uint(a)), "r"(__float_as_uint(b)));
    return r;
}
__device__ __forceinline__ void unpack2(u64 v, float& a, float& b) {
    unsigned x, y;
    asm("mov.b64 {%0, %1}, %2;" : "=r"(x), "=r"(y) : "l"(v));
    a = __uint_as_float(x); b = __uint_as_float(y);
}
__device__ __forceinline__ u64 fma2(u64 a, u64 b, u64 c) {
    u64 d;
    asm("fma.rn.f32x2 %0, %1, %2, %3;" : "=l"(d) : "l"(a), "l"(b), "l"(c));
    return d;
}
__device__ __forceinline__ u64 mul2(u64 a, u64 b) {
    u64 d;
    asm("mul.rn.f32x2 %0, %1, %2;" : "=l"(d) : "l"(a), "l"(b));
    return d;
}

// Interior upsample weight vectors (exact Keys-cubic values, sum = 1):
//   odd  mid-index o: taps x[(o-1)/2-1 .. +2],  W_O
//   even mid-index o: taps x[o/2-2    .. +1],  W_E
#define WO4(a,b,c,d) fmaf(-0.0703125f,(a), fmaf(0.8671875f,(b), fmaf(0.2265625f,(c), -0.0234375f*(d))))
#define WE4(a,b,c,d) fmaf(-0.0234375f,(a), fmaf(0.2265625f,(b), fmaf(0.8671875f,(c), -0.0703125f*(d))))

__device__ __forceinline__ float lrelu(float v) {
    return fmaxf(v, 0.01f * v);   // == LeakyReLU(0.01)
}

// Scalar stage-2 (edge threads): out = W2 . z[0..7]  (9th tap weight is 0)
__device__ __forceinline__ float stage2(const float* __restrict__ z) {
    float a =  fmaf(-0.01171875f, z[0], -0.03515625f * z[1]);
    a = fmaf( 0.11328125f, z[2], a);
    a = fmaf( 0.43359375f, z[3], a);
    a = fmaf( 0.43359375f, z[4], a);
    a = fmaf( 0.11328125f, z[5], a);
    a = fmaf(-0.03515625f, z[6], a);
    a = fmaf(-0.01171875f, z[7], a);
    return a;
}

__global__ void __launch_bounds__(TPB, 3)
cno_lrelu_kernel(const float* __restrict__ x, float* __restrict__ out) {
    __shared__ float xs[IN_SIZE];

    const int row = blockIdx.x;
    const float* __restrict__ xr = x + (size_t)row * IN_SIZE;
    float* __restrict__ orow = out + (size_t)row * OUT_SIZE;

    // Stage row into smem: 512 threads x one float4, coalesced.
    reinterpret_cast<float4*>(xs)[threadIdx.x] =
        reinterpret_cast<const float4*>(xr)[threadIdx.x];
    __syncthreads();

    const int t = threadIdx.x;

    // 12-float window; for interior threads base = 4t-4 covers x[4t-3 .. 4t+6].
    const int base = (t == 0) ? 0 : ((t == TPB - 1) ? (IN_SIZE - 12) : 4 * (t - 1));

    float xv[12];
    #pragma unroll
    for (int q = 0; q < 3; ++q)
        *reinterpret_cast<float4*>(&xv[4 * q]) =
            *reinterpret_cast<const float4*>(&xs[base + 4 * q]);

    float4 o4;

    if (t == 0) {
        // ---- Left edge: outputs 0..3 need mid y[0..10]; y[0..2] are special ----
        float z[11];
        z[0] = fmaf(0.8671875f, xv[0], -0.0703125f * xv[1]) * (1.0f / 0.796875f);
        z[1] = fmaf(0.8671875f, xv[0], fmaf(0.2265625f, xv[1], -0.0234375f * xv[2])) * (1.0f / 1.0703125f);
        z[2] = fmaf(0.2265625f, xv[0], fmaf(0.8671875f, xv[1], -0.0703125f * xv[2])) * (1.0f / 1.0234375f);
        #pragma unroll
        for (int m = 3; m <= 10; ++m) {
            const int s = (m - 3) >> 1;
            z[m] = (m & 1) ? WO4(xv[s], xv[s+1], xv[s+2], xv[s+3])
                           : WE4(xv[s], xv[s+1], xv[s+2], xv[s+3]);
        }
        #pragma unroll
        for (int m = 0; m <= 10; ++m) z[m] = lrelu(z[m]);

        o4.x = fmaf(0.8671875f, z[0] + z[1],
               fmaf(0.2265625f, z[2],
               fmaf(-0.0703125f, z[3], -0.0234375f * z[4]))) * (1.0f / 1.8671875f);
        o4.y = (fmaf(-0.0703125f, z[0],
                fmaf( 0.2265625f, z[1],
                fmaf( 0.8671875f, z[2] + z[3],
                fmaf( 0.2265625f, z[4],
                fmaf(-0.0703125f, z[5], -0.0234375f * z[6])))))) * (1.0f / 2.0234375f);
        o4.z = stage2(z + 1);
        o4.w = stage2(z + 3);
    } else if (t == TPB - 1) {
        // ---- Right edge: outputs 2044..2047 need mid y[4085..4095] ----
        // base = 2036: xv[i] = x[2036+i]. z[j] = y[4085+j].
        float z[11];
        #pragma unroll
        for (int j = 0; j <= 7; ++j) {
            const int s = (j >> 1) + 5;
            z[j] = (j & 1) ? WE4(xv[s], xv[s+1], xv[s+2], xv[s+3])
                           : WO4(xv[s], xv[s+1], xv[s+2], xv[s+3]);
        }
        z[8]  = fmaf(-0.0703125f, xv[9], fmaf(0.8671875f, xv[10], 0.2265625f * xv[11])) * (1.0f / 1.0234375f);
        z[9]  = fmaf(-0.0234375f, xv[9], fmaf(0.2265625f, xv[10], 0.8671875f * xv[11])) * (1.0f / 1.0703125f);
        z[10] = fmaf(-0.0703125f, xv[10], 0.8671875f * xv[11]) * (1.0f / 0.796875f);
        #pragma unroll
        for (int m = 0; m <= 10; ++m) z[m] = lrelu(z[m]);

        o4.x = stage2(z + 0);   // out 2044
        o4.y = stage2(z + 2);   // out 2045
        o4.z = (fmaf(-0.0703125f, z[10],
                fmaf( 0.2265625f, z[9],
                fmaf( 0.8671875f, z[8] + z[7],
                fmaf( 0.2265625f, z[6],
                fmaf(-0.0703125f, z[5], -0.0234375f * z[4])))))) * (1.0f / 2.0234375f);
        o4.w = fmaf(0.8671875f, z[10] + z[9],
               fmaf(0.2265625f, z[8],
               fmaf(-0.0703125f, z[7], -0.0234375f * z[6]))) * (1.0f / 1.8671875f);
    } else {
        // ---- Interior, packed f32x2 ----
        // Pair k (k=0..6): (y[2k], y[2k+1]) both read taps xv[k+1..k+4];
        // lane lo = odd-mid weights W_O, lane hi = even-mid weights W_E.
        const u64 WP0 = pack2(-0.0703125f, -0.0234375f);
        const u64 WP1 = pack2( 0.8671875f,  0.2265625f);
        const u64 WP2 = pack2( 0.2265625f,  0.8671875f);
        const u64 WP3 = pack2(-0.0234375f, -0.0703125f);
        // Stage-2 packed weight pairs: (W2[0],W2[1]) .. (W2[6],W2[7])
        const u64 VP0 = pack2(-0.01171875f, -0.03515625f);
        const u64 VP1 = pack2( 0.11328125f,  0.43359375f);
        const u64 VP2 = pack2( 0.43359375f,  0.11328125f);
        const u64 VP3 = pack2(-0.03515625f, -0.01171875f);

        // Broadcast packs of xv[1..10] (xv[0], xv[11] are alignment padding).
        u64 xx[10];
        #pragma unroll
        for (int i = 0; i < 10; ++i) xx[i] = pack2(xv[i + 1], xv[i + 1]);

        // Rolling accumulation: Z[k] contributes to out[i] for i = k-3..k.
        u64 acc[4];
        #pragma unroll
        for (int k = 0; k < 7; ++k) {
            u64 y2 = mul2(WP0, xx[k]);
            y2 = fma2(WP1, xx[k + 1], y2);
            y2 = fma2(WP2, xx[k + 2], y2);
            y2 = fma2(WP3, xx[k + 3], y2);

            float z0, z1;
            unpack2(y2, z0, z1);
            z0 = fmaxf(z0, 0.01f * z0);
            z1 = fmaxf(z1, 0.01f * z1);
            const u64 zz = pack2(z0, z1);

            if (k <= 3)            acc[k]     = mul2(VP0, zz);
            if (k >= 1 && k <= 4)  acc[k - 1] = fma2(VP1, zz, acc[k - 1]);
            if (k >= 2 && k <= 5)  acc[k - 2] = fma2(VP2, zz, acc[k - 2]);
            if (k >= 3)            acc[k - 3] = fma2(VP3, zz, acc[k - 3]);
        }

        float a0, a1;
        unpack2(acc[0], a0, a1); o4.x = a0 + a1;
        unpack2(acc[1], a0, a1); o4.y = a0 + a1;
        unpack2(acc[2], a0, a1); o4.z = a0 + a1;
        unpack2(acc[3], a0, a1); o4.w = a0 + a1;
    }

    reinterpret_cast<float4*>(orow)[t] = o4;   // coalesced STG.128
}

extern "C" void kernel_launch(void* const* d_in, const int* in_sizes, int n_in,
                              void* d_out, int out_size) {
    const float* x = (const float*)d_in[0];
    float* out = (float*)d_out;
    cno_lrelu_kernel<<<NROWS, TPB>>>(x, out);
}

// round 11
// speedup vs baseline: 6.9452x; 1.2385x over previous
#include <cuda_runtime.h>
#include <math.h>

// CNO_LReLu: antialiased bicubic upsample x2 (2048->4096), LeakyReLU(0.01),
// antialiased bicubic downsample x2 (4096->2048), per (b,c) row. B*C = 8192 rows.
//
// R11: drop the smem staging + __syncthreads (R10 profile: occ 87%, issue 52%,
// nothing saturated -> barrier-coupled load latency was the critical path).
// Each thread loads its 12-float window directly with 3 overlapping LDG.128;
// warps proceed independently. l1tex ops/thread drop 5 -> 3. No smem ->
// 4 CTAs/SM. Interior stays packed f32x2.

#define IN_SIZE  2048
#define OUT_SIZE 2048
#define NROWS    8192
#define TPB      512        // 4 outputs per thread

typedef unsigned long long u64;

__device__ __forceinline__ u64 pack2(float a, float b) {
    u64 r;
    asm("mov.b64 %0, {%1, %2};" : "=l"(r)
        : "r"(__float_as_uint(a)), "r"(__float_as_uint(b)));
    return r;
}
__device__ __forceinline__ void unpack2(u64 v, float& a, float& b) {
    unsigned x, y;
    asm("mov.b64 {%0, %1}, %2;" : "=r"(x), "=r"(y) : "l"(v));
    a = __uint_as_float(x); b = __uint_as_float(y);
}
__device__ __forceinline__ u64 fma2(u64 a, u64 b, u64 c) {
    u64 d;
    asm("fma.rn.f32x2 %0, %1, %2, %3;" : "=l"(d) : "l"(a), "l"(b), "l"(c));
    return d;
}
__device__ __forceinline__ u64 mul2(u64 a, u64 b) {
    u64 d;
    asm("mul.rn.f32x2 %0, %1, %2;" : "=l"(d) : "l"(a), "l"(b));
    return d;
}

// Interior upsample weight vectors (exact Keys-cubic values, sum = 1):
//   odd  mid-index o: taps x[(o-1)/2-1 .. +2],  W_O
//   even mid-index o: taps x[o/2-2    .. +1],  W_E
#define WO4(a,b,c,d) fmaf(-0.0703125f,(a), fmaf(0.8671875f,(b), fmaf(0.2265625f,(c), -0.0234375f*(d))))
#define WE4(a,b,c,d) fmaf(-0.0234375f,(a), fmaf(0.2265625f,(b), fmaf(0.8671875f,(c), -0.0703125f*(d))))

__device__ __forceinline__ float lrelu(float v) {
    return fmaxf(v, 0.01f * v);   // == LeakyReLU(0.01)
}

// Scalar stage-2 (edge threads): out = W2 . z[0..7]  (9th tap weight is 0)
__device__ __forceinline__ float stage2(const float* __restrict__ z) {
    float a =  fmaf(-0.01171875f, z[0], -0.03515625f * z[1]);
    a = fmaf( 0.11328125f, z[2], a);
    a = fmaf( 0.43359375f, z[3], a);
    a = fmaf( 0.43359375f, z[4], a);
    a = fmaf( 0.11328125f, z[5], a);
    a = fmaf(-0.03515625f, z[6], a);
    a = fmaf(-0.01171875f, z[7], a);
    return a;
}

__global__ void __launch_bounds__(TPB, 4)
cno_lrelu_kernel(const float* __restrict__ x, float* __restrict__ out) {
    const int row = blockIdx.x;
    const float* __restrict__ xr = x + (size_t)row * IN_SIZE;
    float* __restrict__ orow = out + (size_t)row * OUT_SIZE;

    const int t = threadIdx.x;

    // 12-float window; for interior threads base = 4t-4 covers x[4t-3 .. 4t+6].
    const int base = (t == 0) ? 0 : ((t == TPB - 1) ? (IN_SIZE - 12) : 4 * (t - 1));

    // Direct global loads: 3 overlapping LDG.128 (16B-aligned; L1-friendly:
    // each 16B chunk is shared by 3 adjacent threads).
    float xv[12];
    #pragma unroll
    for (int q = 0; q < 3; ++q)
        *reinterpret_cast<float4*>(&xv[4 * q]) =
            *reinterpret_cast<const float4*>(&xr[base + 4 * q]);

    float4 o4;

    if (t == 0) {
        // ---- Left edge: outputs 0..3 need mid y[0..10]; y[0..2] are special ----
        float z[11];
        z[0] = fmaf(0.8671875f, xv[0], -0.0703125f * xv[1]) * (1.0f / 0.796875f);
        z[1] = fmaf(0.8671875f, xv[0], fmaf(0.2265625f, xv[1], -0.0234375f * xv[2])) * (1.0f / 1.0703125f);
        z[2] = fmaf(0.2265625f, xv[0], fmaf(0.8671875f, xv[1], -0.0703125f * xv[2])) * (1.0f / 1.0234375f);
        #pragma unroll
        for (int m = 3; m <= 10; ++m) {
            const int s = (m - 3) >> 1;
            z[m] = (m & 1) ? WO4(xv[s], xv[s+1], xv[s+2], xv[s+3])
                           : WE4(xv[s], xv[s+1], xv[s+2], xv[s+3]);
        }
        #pragma unroll
        for (int m = 0; m <= 10; ++m) z[m] = lrelu(z[m]);

        o4.x = fmaf(0.8671875f, z[0] + z[1],
               fmaf(0.2265625f, z[2],
               fmaf(-0.0703125f, z[3], -0.0234375f * z[4]))) * (1.0f / 1.8671875f);
        o4.y = (fmaf(-0.0703125f, z[0],
                fmaf( 0.2265625f, z[1],
                fmaf( 0.8671875f, z[2] + z[3],
                fmaf( 0.2265625f, z[4],
                fmaf(-0.0703125f, z[5], -0.0234375f * z[6])))))) * (1.0f / 2.0234375f);
        o4.z = stage2(z + 1);
        o4.w = stage2(z + 3);
    } else if (t == TPB - 1) {
        // ---- Right edge: outputs 2044..2047 need mid y[4085..4095] ----
        // base = 2036: xv[i] = x[2036+i]. z[j] = y[4085+j].
        float z[11];
        #pragma unroll
        for (int j = 0; j <= 7; ++j) {
            const int s = (j >> 1) + 5;
            z[j] = (j & 1) ? WE4(xv[s], xv[s+1], xv[s+2], xv[s+3])
                           : WO4(xv[s], xv[s+1], xv[s+2], xv[s+3]);
        }
        z[8]  = fmaf(-0.0703125f, xv[9], fmaf(0.8671875f, xv[10], 0.2265625f * xv[11])) * (1.0f / 1.0234375f);
        z[9]  = fmaf(-0.0234375f, xv[9], fmaf(0.2265625f, xv[10], 0.8671875f * xv[11])) * (1.0f / 1.0703125f);
        z[10] = fmaf(-0.0703125f, xv[10], 0.8671875f * xv[11]) * (1.0f / 0.796875f);
        #pragma unroll
        for (int m = 0; m <= 10; ++m) z[m] = lrelu(z[m]);

        o4.x = stage2(z + 0);   // out 2044
        o4.y = stage2(z + 2);   // out 2045
        o4.z = (fmaf(-0.0703125f, z[10],
                fmaf( 0.2265625f, z[9],
                fmaf( 0.8671875f, z[8] + z[7],
                fmaf( 0.2265625f, z[6],
                fmaf(-0.0703125f, z[5], -0.0234375f * z[4])))))) * (1.0f / 2.0234375f);
        o4.w = fmaf(0.8671875f, z[10] + z[9],
               fmaf(0.2265625f, z[8],
               fmaf(-0.0703125f, z[7], -0.0234375f * z[6]))) * (1.0f / 1.8671875f);
    } else {
        // ---- Interior, packed f32x2 ----
        // Pair k (k=0..6): (y[2k], y[2k+1]) both read taps xv[k+1..k+4];
        // lane lo = odd-mid weights W_O, lane hi = even-mid weights W_E.
        const u64 WP0 = pack2(-0.0703125f, -0.0234375f);
        const u64 WP1 = pack2( 0.8671875f,  0.2265625f);
        const u64 WP2 = pack2( 0.2265625f,  0.8671875f);
        const u64 WP3 = pack2(-0.0234375f, -0.0703125f);
        // Stage-2 packed weight pairs: (W2[0],W2[1]) .. (W2[6],W2[7])
        const u64 VP0 = pack2(-0.01171875f, -0.03515625f);
        const u64 VP1 = pack2( 0.11328125f,  0.43359375f);
        const u64 VP2 = pack2( 0.43359375f,  0.11328125f);
        const u64 VP3 = pack2(-0.03515625f, -0.01171875f);

        // Broadcast packs of xv[1..10] (xv[0], xv[11] are alignment padding).
        u64 xx[10];
        #pragma unroll
        for (int i = 0; i < 10; ++i) xx[i] = pack2(xv[i + 1], xv[i + 1]);

        // Rolling accumulation: Z[k] contributes to out[i] for i = k-3..k.
        u64 acc[4];
        #pragma unroll
        for (int k = 0; k < 7; ++k) {
            u64 y2 = mul2(WP0, xx[k]);
            y2 = fma2(WP1, xx[k + 1], y2);
            y2 = fma2(WP2, xx[k + 2], y2);
            y2 = fma2(WP3, xx[k + 3], y2);

            float z0, z1;
            unpack2(y2, z0, z1);
            z0 = fmaxf(z0, 0.01f * z0);
            z1 = fmaxf(z1, 0.01f * z1);
            const u64 zz = pack2(z0, z1);

            if (k <= 3)            acc[k]     = mul2(VP0, zz);
            if (k >= 1 && k <= 4)  acc[k - 1] = fma2(VP1, zz, acc[k - 1]);
            if (k >= 2 && k <= 5)  acc[k - 2] = fma2(VP2, zz, acc[k - 2]);
            if (k >= 3)            acc[k - 3] = fma2(VP3, zz, acc[k - 3]);
        }

        float a0, a1;
        unpack2(acc[0], a0, a1); o4.x = a0 + a1;
        unpack2(acc[1], a0, a1); o4.y = a0 + a1;
        unpack2(acc[2], a0, a1); o4.z = a0 + a1;
        unpack2(acc[3], a0, a1); o4.w = a0 + a1;
    }

    reinterpret_cast<float4*>(orow)[t] = o4;   // coalesced STG.128
}

extern "C" void kernel_launch(void* const* d_in, const int* in_sizes, int n_in,
                              void* d_out, int out_size) {
    const float* x = (const float*)d_in[0];
    float* out = (float*)d_out;
    cno_lrelu_kernel<<<NROWS, TPB>>>(x, out);
}